// round 1
// baseline (speedup 1.0000x reference)
#include <cuda_runtime.h>
#include <cstdint>

#define FM 0xFFFFFFFFu

constexpr int NUSERS = 100000;
constexpr int NITEMS = 50000;
constexpr int NNODES = NUSERS + NITEMS;   // 150000
constexpr int NNZV   = 2000000;
constexpr int EMBV   = 100;
constexpr int BATCHV = 16384;
constexpr int V4     = EMBV / 4;          // 25 float4 per row
constexpr int STILE  = 1024;
constexpr int NBLK1  = (NNODES + STILE - 1) / STILE; // 147

// ---- scratch (static device arrays; no runtime allocation) ----
__device__ int    g_cnt[NNODES];
__device__ int    g_scan[NNODES];
__device__ int    g_bsum[256];
__device__ int    g_rp[NNODES + 1];
__device__ int    g_cur[NNODES];
__device__ int2   g_edge[NNZV];                       // {col, val_bits}, CSR-ordered
__device__ float4 g_e1[(size_t)NNODES * V4];          // layer-1 output, 60 MB
__device__ float4 g_hbuf[(size_t)BATCHV * 2 * V4];    // [B, 200] MLP input, 13 MB

// ================= CSR build =================

__global__ void k_zero_cnt() {
    int i = blockIdx.x * blockDim.x + threadIdx.x;
    if (i < NNODES) g_cnt[i] = 0;
}

__global__ void k_hist(const int* __restrict__ row) {
    int e = blockIdx.x * blockDim.x + threadIdx.x;
    if (e < NNZV) atomicAdd(&g_cnt[row[e]], 1);
}

__global__ void k_scan1() {
    __shared__ int sm[STILE];
    int i = blockIdx.x * STILE + threadIdx.x;
    int v = (i < NNODES) ? g_cnt[i] : 0;
    sm[threadIdx.x] = v;
    __syncthreads();
    for (int off = 1; off < STILE; off <<= 1) {
        int t = (threadIdx.x >= off) ? sm[threadIdx.x - off] : 0;
        __syncthreads();
        sm[threadIdx.x] += t;
        __syncthreads();
    }
    if (i < NNODES) g_scan[i] = sm[threadIdx.x];
    if (threadIdx.x == STILE - 1) g_bsum[blockIdx.x] = sm[STILE - 1];
}

__global__ void k_scan2() {
    __shared__ int sm[256];
    int v = (threadIdx.x < NBLK1) ? g_bsum[threadIdx.x] : 0;
    sm[threadIdx.x] = v;
    __syncthreads();
    for (int off = 1; off < 256; off <<= 1) {
        int t = (threadIdx.x >= off) ? sm[threadIdx.x - off] : 0;
        __syncthreads();
        sm[threadIdx.x] += t;
        __syncthreads();
    }
    if (threadIdx.x < NBLK1) g_bsum[threadIdx.x] = sm[threadIdx.x];
}

__global__ void k_rowptr() {
    int i = blockIdx.x * blockDim.x + threadIdx.x;
    if (i < NNODES) {
        int bi  = i / STILE;
        int add = (bi > 0) ? g_bsum[bi - 1] : 0;
        g_rp[i + 1] = g_scan[i] + add;
        if (i == 0) g_rp[0] = 0;
    }
}

__global__ void k_cursor() {
    int i = blockIdx.x * blockDim.x + threadIdx.x;
    if (i < NNODES) g_cur[i] = g_rp[i];
}

__global__ void k_scatter(const int* __restrict__ row, const int* __restrict__ col,
                          const float* __restrict__ val) {
    int e = blockIdx.x * blockDim.x + threadIdx.x;
    if (e < NNZV) {
        int p = atomicAdd(&g_cur[row[e]], 1);
        g_edge[p] = make_int2(col[e], __float_as_int(val[e]));
    }
}

// ================= Layer 1: e1 = A @ ego (full, warp-per-row) =================

__global__ void k_spmm1(const float* __restrict__ ue, const float* __restrict__ ie) {
    int warp = (blockIdx.x * blockDim.x + threadIdx.x) >> 5;
    int lane = threadIdx.x & 31;
    if (warp >= NNODES) return;
    int s = g_rp[warp], e = g_rp[warp + 1];
    float4 acc = make_float4(0.f, 0.f, 0.f, 0.f);
    for (int k = s; k < e; k++) {
        int2 ed = __ldg(&g_edge[k]);                 // broadcast (same addr all lanes)
        float v = __int_as_float(ed.y);
        const float4* x4 = (ed.x < NUSERS)
            ? (const float4*)ue + (size_t)ed.x * V4
            : (const float4*)ie + (size_t)(ed.x - NUSERS) * V4;
        if (lane < V4) {
            float4 xv = __ldg(&x4[lane]);
            acc.x += v * xv.x; acc.y += v * xv.y;
            acc.z += v * xv.z; acc.w += v * xv.w;
        }
    }
    if (lane < V4) g_e1[(size_t)warp * V4 + lane] = acc;
}

// ====== Layer 2 restricted to batch rows + final mean + gather into h ======

__global__ void k_gather2(const float* __restrict__ ue, const float* __restrict__ ie,
                          const int* __restrict__ uidx, const int* __restrict__ iidx) {
    int warp = (blockIdx.x * blockDim.x + threadIdx.x) >> 5;
    int lane = threadIdx.x & 31;
    if (warp >= 2 * BATCHV) return;
    int b = warp >> 1, side = warp & 1;
    int row;
    const float4* ego4;
    if (side == 0) {
        int u = uidx[b];
        row = u;
        ego4 = (const float4*)ue + (size_t)u * V4;
    } else {
        int it = iidx[b];
        row = it + NUSERS;
        ego4 = (const float4*)ie + (size_t)it * V4;
    }
    int s = g_rp[row], e = g_rp[row + 1];
    float4 acc = make_float4(0.f, 0.f, 0.f, 0.f);
    for (int k = s; k < e; k++) {
        int2 ed = __ldg(&g_edge[k]);
        float v = __int_as_float(ed.y);
        if (lane < V4) {
            float4 xv = g_e1[(size_t)ed.x * V4 + lane];
            acc.x += v * xv.x; acc.y += v * xv.y;
            acc.z += v * xv.z; acc.w += v * xv.w;
        }
    }
    if (lane < V4) {
        float4 eg  = __ldg(&ego4[lane]);
        float4 e1r = g_e1[(size_t)row * V4 + lane];
        const float inv3 = 1.f / 3.f;
        float4 f;
        f.x = (eg.x + e1r.x + acc.x) * inv3;
        f.y = (eg.y + e1r.y + acc.y) * inv3;
        f.z = (eg.z + e1r.z + acc.z) * inv3;
        f.w = (eg.w + e1r.w + acc.w) * inv3;
        g_hbuf[(size_t)b * (2 * V4) + side * V4 + lane] = f;
    }
}

// ================= MLP: [B,200] -> 64 (relu) -> 32 -> 1 =================
// warp-per-row, 8 rows per 256-thread block; W1 tiled through smem in 2 k-passes.

__global__ void k_mlp(const float* __restrict__ W1, const float* __restrict__ b1,
                      const float* __restrict__ W2, const float* __restrict__ b2,
                      const float* __restrict__ W3, const float* __restrict__ b3,
                      float* __restrict__ out) {
    __shared__ float W1t[100 * 64];   // 25.6 KB tile (half of W1 per pass)
    __shared__ float hs[8 * 200];     // 6.4 KB staged inputs
    __shared__ float W2s[64 * 32];    // 8 KB
    __shared__ float b1s[64];
    __shared__ float b2s[32];
    __shared__ float W3s[32];
    __shared__ float b3s;

    int tid = threadIdx.x;
    int w = tid >> 5, lane = tid & 31;

    if (tid < 64) b1s[tid] = b1[tid];
    else if (tid < 96) b2s[tid - 64] = b2[tid - 64];
    else if (tid < 128) W3s[tid - 96] = W3[tid - 96];
    else if (tid == 128) b3s = b3[0];
    for (int t = tid; t < 64 * 32; t += 256) W2s[t] = W2[t];

    int b = blockIdx.x * 8 + w;
    const float* hrow = (const float*)g_hbuf + (size_t)b * 200;
    for (int t = lane; t < 200; t += 32) hs[w * 200 + t] = hrow[t];
    __syncthreads();

    float acc0 = b1s[lane], acc1 = b1s[lane + 32];
    for (int pass = 0; pass < 2; pass++) {
        for (int t = tid; t < 100 * 64; t += 256) W1t[t] = W1[pass * 6400 + t];
        __syncthreads();
        int kb = pass * 100;
#pragma unroll 4
        for (int kk = 0; kk < 100; kk++) {
            float hk = hs[w * 200 + kb + kk];
            acc0 += hk * W1t[kk * 64 + lane];
            acc1 += hk * W1t[kk * 64 + lane + 32];
        }
        __syncthreads();
    }

    float h1a = fmaxf(acc0, 0.f);
    float h1b = fmaxf(acc1, 0.f);

    float acc2 = b2s[lane];
#pragma unroll
    for (int j = 0; j < 32; j++) {
        float hj = __shfl_sync(FM, h1a, j);
        acc2 += hj * W2s[j * 32 + lane];
    }
#pragma unroll
    for (int j = 0; j < 32; j++) {
        float hj = __shfl_sync(FM, h1b, j);
        acc2 += hj * W2s[(j + 32) * 32 + lane];
    }

    float p = acc2 * W3s[lane];
#pragma unroll
    for (int o = 16; o > 0; o >>= 1) p += __shfl_xor_sync(FM, p, o);
    if (lane == 0) out[b] = p + b3s;
}

// ================= launch =================

extern "C" void kernel_launch(void* const* d_in, const int* in_sizes, int n_in,
                              void* d_out, int out_size) {
    const float* user_emb = (const float*)d_in[0];
    const float* item_emb = (const float*)d_in[1];
    const int*   adj_row  = (const int*)d_in[2];
    const int*   adj_col  = (const int*)d_in[3];
    const float* adj_val  = (const float*)d_in[4];
    const int*   uidx     = (const int*)d_in[5];
    const int*   iidx     = (const int*)d_in[6];
    const float* W1 = (const float*)d_in[7];
    const float* b1 = (const float*)d_in[8];
    const float* W2 = (const float*)d_in[9];
    const float* b2 = (const float*)d_in[10];
    const float* W3 = (const float*)d_in[11];
    const float* b3 = (const float*)d_in[12];
    float* out = (float*)d_out;

    // CSR build (every launch; deterministic work)
    k_zero_cnt<<<(NNODES + 255) / 256, 256>>>();
    k_hist<<<(NNZV + 255) / 256, 256>>>(adj_row);
    k_scan1<<<NBLK1, STILE>>>();
    k_scan2<<<1, 256>>>();
    k_rowptr<<<(NNODES + 255) / 256, 256>>>();
    k_cursor<<<(NNODES + 255) / 256, 256>>>();
    k_scatter<<<(NNZV + 255) / 256, 256>>>(adj_row, adj_col, adj_val);

    // Layer 1 (full), layer 2 (batch rows only) + final + gather
    k_spmm1<<<(NNODES * 32) / 256, 256>>>(user_emb, item_emb);
    k_gather2<<<(2 * BATCHV * 32) / 256, 256>>>(user_emb, item_emb, uidx, iidx);

    // MLP
    k_mlp<<<BATCHV / 8, 256>>>(W1, b1, W2, b2, W3, b3, out);
}